// round 16
// baseline (speedup 1.0000x reference)
#include <cuda_runtime.h>
#include <cuda_bf16.h>
#include <cstdint>

// Problem: B=8, CIN=256, COUT=512, DK=DV=256, NH=8, H=W=32
// R16: conv_mma re-tiled 256x128 (warp 64x64) to cut smem-crossbar traffic;
//      preps reverted to R14 split form. Attention = R14 proven state.

// Scratch (static device globals: allocation-free rule)
__device__ __nv_bfloat16 g_colh[8192 * 2304];  // im2col hi plane [n][k]
__device__ __nv_bfloat16 g_coll[8192 * 2304];  // im2col lo plane
__device__ __nv_bfloat16 g_wh[1024 * 2304];    // weights hi [co][k]
__device__ __nv_bfloat16 g_wl[1024 * 2304];    // weights lo
__device__ float g_qkv[8 * 768 * 1024];        // qkv conv output (b, 768, HW)
__device__ float g_att[8 * 256 * 1024];        // attention out, (b, C, H, W)

// attention operand planes
__device__ __nv_bfloat16 g_qh[64 * 1024 * 32]; // Q hi [bh][m][d] (scaled)
__device__ __nv_bfloat16 g_ql[64 * 1024 * 32];
__device__ __nv_bfloat16 g_kh[64 * 1024 * 32]; // K hi [bh][n][d]
__device__ __nv_bfloat16 g_kl[64 * 1024 * 32];
__device__ __nv_bfloat16 g_vh[64 * 32 * 1024]; // V hi [bh][d][n]
__device__ __nv_bfloat16 g_vl[64 * 32 * 1024];
__device__ float g_relw[64 * 1024 * 32];       // rotated rel-w [bh][m][ny]
__device__ float g_relh[64 * 1024 * 32];       // rotated rel-h [bh][m][nx]

// conv1x1 operand planes
__device__ __nv_bfloat16 g_atth[8192 * 256];   // att hi [b*1024+p][ci]
__device__ __nv_bfloat16 g_attl[8192 * 256];
__device__ __nv_bfloat16 g_wath[256 * 256];    // w_att hi [co][ci]
__device__ __nv_bfloat16 g_watl[256 * 256];

// ---------------------------------------------------------------------------
// Helpers (sm_80-era ISA only: cp.async, ldmatrix, mma.sync — safe on sm_103)
// ---------------------------------------------------------------------------
__device__ __forceinline__ uint32_t smem_u32(const void* p) {
    uint32_t a;
    asm("{ .reg .u64 t; cvta.to.shared.u64 t, %1; cvt.u32.u64 %0, t; }"
        : "=r"(a) : "l"(p));
    return a;
}
#define SWZ128(o) ((o) ^ (((o) >> 3) & 0x70))
#define SWZ64(o)  ((o) ^ (((o) >> 3) & 0x30))

#define CP_ASYNC16(dst, src) \
    asm volatile("cp.async.cg.shared.global [%0], [%1], 16;" :: "r"(dst), "l"(src))
#define CP_COMMIT() asm volatile("cp.async.commit_group;" ::: "memory")
#define CP_WAIT(n)  asm volatile("cp.async.wait_group %0;" :: "n"(n) : "memory")

__device__ __forceinline__ void ldsm4(uint32_t* r, uint32_t a) {
    asm volatile("ldmatrix.sync.aligned.m8n8.x4.shared.b16 {%0,%1,%2,%3}, [%4];"
                 : "=r"(r[0]), "=r"(r[1]), "=r"(r[2]), "=r"(r[3]) : "r"(a));
}
__device__ __forceinline__ void mma16816(float* c, const uint32_t* a, const uint32_t* b) {
    asm volatile(
        "mma.sync.aligned.m16n8k16.row.col.f32.bf16.bf16.f32 "
        "{%0,%1,%2,%3}, {%4,%5,%6,%7}, {%8,%9}, {%0,%1,%2,%3};"
        : "+f"(c[0]), "+f"(c[1]), "+f"(c[2]), "+f"(c[3])
        : "r"(a[0]), "r"(a[1]), "r"(a[2]), "r"(a[3]), "r"(b[0]), "r"(b[1]));
}
__device__ __forceinline__ float ex2(float x) {
    float y; asm("ex2.approx.f32 %0, %1;" : "=f"(y) : "f"(x)); return y;
}

// ---------------------------------------------------------------------------
// Prep kernels (R14 split form)
// ---------------------------------------------------------------------------
__global__ void im2col_k(const float* __restrict__ x) {
    int k = blockIdx.x * 256 + threadIdx.x;   // 0..2303 (grid.x = 9)
    int n = blockIdx.y;                       // 0..8191
    int b = n >> 10, p = n & 1023, py = p >> 5, px = p & 31;
    int ci = k / 9, r = k - ci * 9;
    int ky = r / 3, kx = r - ky * 3;
    int gy = py + ky - 1, gx = px + kx - 1;
    float v = 0.f;
    if ((unsigned)gy < 32u && (unsigned)gx < 32u)
        v = x[((b * 256 + ci) * 32 + gy) * 32 + gx];
    __nv_bfloat16 hi = __float2bfloat16(v);
    float lo = v - __bfloat162float(hi);
    g_colh[(size_t)n * 2304 + k] = hi;
    g_coll[(size_t)n * 2304 + k] = __float2bfloat16(lo);
}

__global__ void prep_w(const float* __restrict__ wc, const float* __restrict__ wq) {
    int k = blockIdx.x * 256 + threadIdx.x;   // grid.x = 9
    int co = blockIdx.y;                      // 0..1023
    float v = (co < 256) ? wc[co * 2304 + k] : wq[(co - 256) * 2304 + k];
    __nv_bfloat16 hi = __float2bfloat16(v);
    float lo = v - __bfloat162float(hi);
    g_wh[(size_t)co * 2304 + k] = hi;
    g_wl[(size_t)co * 2304 + k] = __float2bfloat16(lo);
}

__global__ void prep_watt(const float* __restrict__ wa) {
    int idx = blockIdx.x * 256 + threadIdx.x; // 65536, [co][ci] direct
    float v = wa[idx];
    __nv_bfloat16 hi = __float2bfloat16(v);
    g_wath[idx] = hi;
    g_watl[idx] = __float2bfloat16(v - __bfloat162float(hi));
}

// att f32 [b][ci][p] -> bf16 hi/lo [b*1024+p][ci] (smem transpose)
__global__ __launch_bounds__(256) void att_repack() {
    __shared__ float ts[32][33];
    const int b = blockIdx.z;
    const int ci0 = blockIdx.y * 32;
    const int p0 = blockIdx.x * 32;
    const int t = threadIdx.x;
#pragma unroll
    for (int i = 0; i < 4; ++i) {
        int idx = t + i * 256;
        int ci_l = idx >> 5, p_l = idx & 31;
        ts[ci_l][p_l] = g_att[((size_t)b * 256 + ci0 + ci_l) * 1024 + p0 + p_l];
    }
    __syncthreads();
#pragma unroll
    for (int i = 0; i < 4; ++i) {
        int idx = t + i * 256;
        int p_l = idx >> 5, ci_l = idx & 31;
        float v = ts[ci_l][p_l];
        __nv_bfloat16 hi = __float2bfloat16(v);
        size_t o = ((size_t)b * 1024 + p0 + p_l) * 256 + ci0 + ci_l;
        g_atth[o] = hi;
        g_attl[o] = __float2bfloat16(v - __bfloat162float(hi));
    }
}

// ---------------------------------------------------------------------------
// conv3x3 split-bf16 GEMM. R16: CTA tile 256px x 128co, warp tile 64x64,
// 8 warps (4M x 2N), K=2304 in 72 chunks of 32, 2-stage 48KB pipeline.
// Cuts LDSM redundancy: A read by 2 warps, B by 4 -> crossbar below tensor.
// ---------------------------------------------------------------------------
__global__ __launch_bounds__(256, 1) void conv_mma(
    const float* __restrict__ bconv,
    const float* __restrict__ bqkv,
    float* __restrict__ out) {
    extern __shared__ char dsm[];
    char* sb = (char*)(((uintptr_t)dsm + 1023) & ~(uintptr_t)1023);
    const uint32_t sbu = smem_u32(sb);

    const int t = threadIdx.x;
    const int lane = t & 31;
    const int wid = t >> 5;
    const int warpM = wid & 3;            // 4 M-warps: 64 px each
    const int warpN = wid >> 2;           // 2 N-warps: 64 co each
    const int nBase = blockIdx.x * 256;   // pixel tile
    const int coBase = blockIdx.y * 128;  // channel tile

    const int la = lane & 15;
    const int lb = (lane >> 4) << 4;
    const int bg = lane >> 3;
    const int brow = ((bg >> 1) << 3) + (lane & 7);
    const int bch = (bg & 1) << 4;

    float acc[128];
#pragma unroll
    for (int i = 0; i < 128; ++i) acc[i] = 0.f;

    const int lrow = t >> 2;   // 0..63
    const int lj = t & 3;

    // buffer: A hi 16K | A lo 16K | B hi 8K | B lo 8K = 48KB
#define CM_LOAD(buf, s_) do { \
        const size_t kb2 = (size_t)(s_) * 64; \
        uint32_t d0 = sbu + (buf) * 49152; \
        _Pragma("unroll") \
        for (int i = 0; i < 4; ++i) { \
            int row = lrow + i * 64; \
            uint32_t sw = SWZ64(row * 64 + lj * 16); \
            CP_ASYNC16(d0 + sw,         (const char*)g_colh + (size_t)(nBase + row) * 4608 + kb2 + lj * 16); \
            CP_ASYNC16(d0 + 16384 + sw, (const char*)g_coll + (size_t)(nBase + row) * 4608 + kb2 + lj * 16); \
        } \
        _Pragma("unroll") \
        for (int i = 0; i < 2; ++i) { \
            int row = lrow + i * 64; \
            uint32_t sw = SWZ64(row * 64 + lj * 16); \
            CP_ASYNC16(d0 + 32768 + sw, (const char*)g_wh + (size_t)(coBase + row) * 4608 + kb2 + lj * 16); \
            CP_ASYNC16(d0 + 40960 + sw, (const char*)g_wl + (size_t)(coBase + row) * 4608 + kb2 + lj * 16); \
        } \
    } while (0)

    CM_LOAD(0, 0);
    CP_COMMIT();

#pragma unroll 1
    for (int s = 0; s < 72; ++s) {
        if (s < 71) {
            CM_LOAD((s + 1) & 1, s + 1);
            CP_COMMIT();
            CP_WAIT(1);
        } else {
            CP_WAIT(0);
        }
        __syncthreads();

        const uint32_t base = sbu + (s & 1) * 49152;
#pragma unroll
        for (int kk = 0; kk < 2; ++kk) {
            uint32_t bh[16], bl[16];
#pragma unroll
            for (int ntb = 0; ntb < 4; ++ntb) {
                uint32_t off = SWZ64((warpN * 64 + ntb * 16 + brow) * 64 + kk * 32 + bch);
                ldsm4(bh + 4 * ntb, base + 32768 + off);
                ldsm4(bl + 4 * ntb, base + 40960 + off);
            }
#pragma unroll
            for (int mt = 0; mt < 4; ++mt) {
                uint32_t ah[4], al[4];
                uint32_t off = SWZ64((warpM * 64 + mt * 16 + la) * 64 + kk * 32 + lb);
                ldsm4(ah, base + off);
                ldsm4(al, base + 16384 + off);
#pragma unroll
                for (int nt = 0; nt < 8; ++nt) {
                    float* c = acc + (mt * 8 + nt) * 4;
                    mma16816(c, ah, bh + 2 * nt);
                    mma16816(c, ah, bl + 2 * nt);
                    mma16816(c, al, bh + 2 * nt);
                }
            }
        }
        __syncthreads();
    }

    // Epilogue in two 128-px halves through smem (128co x 132px floats)
    float* sf = (float*)sb;
    const int b = nBase >> 10;
#pragma unroll 1
    for (int half = 0; half < 2; ++half) {
        __syncthreads();
        if ((warpM >> 1) == half) {
#pragma unroll
            for (int mt = 0; mt < 4; ++mt)
#pragma unroll
                for (int nt = 0; nt < 8; ++nt) {
                    const float* c = acc + (mt * 8 + nt) * 4;
                    int px0 = (warpM & 1) * 64 + mt * 16 + (lane >> 2);
                    int co0 = warpN * 64 + nt * 8 + (lane & 3) * 2;
                    sf[co0 * 132 + px0]           = c[0];
                    sf[(co0 + 1) * 132 + px0]     = c[1];
                    sf[co0 * 132 + px0 + 8]       = c[2];
                    sf[(co0 + 1) * 132 + px0 + 8] = c[3];
                }
        }
        __syncthreads();

        const int p0 = (nBase & 1023) + half * 128;
#pragma unroll 4
        for (int i = 0; i < 64; ++i) {
            int idx = t + i * 256;
            int co_l = idx >> 7;
            int px_l = idx & 127;
            float v = sf[co_l * 132 + px_l];
            int co = coBase + co_l;
            int p = p0 + px_l;
            if (coBase < 256) {
                out[((size_t)b * 512 + co) * 1024 + p] = v + __ldg(&bconv[co]);
            } else {
                g_qkv[((size_t)b * 768 + co - 256) * 1024 + p] = v + __ldg(&bqkv[co - 256]);
            }
        }
    }
}

// ---------------------------------------------------------------------------
// conv1x1 split-bf16 GEMM. CTA tile 128px x 128co. K=256 in 8 chunks of 32.
// ---------------------------------------------------------------------------
__global__ __launch_bounds__(256, 2) void conv1x1_mma(
    const float* __restrict__ batt,
    float* __restrict__ out) {
    extern __shared__ char dsm[];
    char* sb = (char*)(((uintptr_t)dsm + 1023) & ~(uintptr_t)1023);
    const uint32_t sbu = smem_u32(sb);

    const int t = threadIdx.x;
    const int lane = t & 31;
    const int wid = t >> 5;
    const int warpM = wid >> 1;
    const int warpN = wid & 1;
    const int nBase = blockIdx.x * 128;
    const int coBase = blockIdx.y * 128;

    const int la = lane & 15;
    const int lb = (lane >> 4) << 4;
    const int bg = lane >> 3;
    const int brow = ((bg >> 1) << 3) + (lane & 7);
    const int bch = (bg & 1) << 4;

    float acc[64];
#pragma unroll
    for (int i = 0; i < 64; ++i) acc[i] = 0.f;

    const int lrow = t >> 2;
    const int lj = t & 3;

#define LOAD_STAGE1x1(buf, s_) do { \
        const size_t kb2 = (size_t)(s_) * 64; \
        uint32_t d0 = sbu + (buf) * 32768; \
        _Pragma("unroll") \
        for (int i = 0; i < 2; ++i) { \
            int row = lrow + i * 64; \
            uint32_t sw = SWZ64(row * 64 + lj * 16); \
            CP_ASYNC16(d0 + sw,         (const char*)g_atth + (size_t)(nBase + row) * 512 + kb2 + lj * 16); \
            CP_ASYNC16(d0 + 8192 + sw,  (const char*)g_attl + (size_t)(nBase + row) * 512 + kb2 + lj * 16); \
            CP_ASYNC16(d0 + 16384 + sw, (const char*)g_wath + (size_t)(coBase + row) * 512 + kb2 + lj * 16); \
            CP_ASYNC16(d0 + 24576 + sw, (const char*)g_watl + (size_t)(coBase + row) * 512 + kb2 + lj * 16); \
        } \
    } while (0)

    LOAD_STAGE1x1(0, 0);
    CP_COMMIT();
    LOAD_STAGE1x1(1, 1);
    CP_COMMIT();
    CP_WAIT(1);

    int cbuf = 0;
    int lbuf = 2;
#pragma unroll 1
    for (int s = 0; s < 8; ++s) {
        __syncthreads();
        if (s + 2 < 8) {
            LOAD_STAGE1x1(lbuf, s + 2);
            CP_COMMIT();
        }

        const uint32_t base = sbu + cbuf * 32768;
#pragma unroll
        for (int kk = 0; kk < 2; ++kk) {
            uint32_t bh[16], bl[16];
#pragma unroll
            for (int ntb = 0; ntb < 4; ++ntb) {
                uint32_t off = SWZ64((warpN * 64 + ntb * 16 + brow) * 64 + kk * 32 + bch);
                ldsm4(bh + 4 * ntb, base + 16384 + off);
                ldsm4(bl + 4 * ntb, base + 24576 + off);
            }
#pragma unroll
            for (int mt = 0; mt < 2; ++mt) {
                uint32_t ah[4], al[4];
                uint32_t off = SWZ64((warpM * 32 + mt * 16 + la) * 64 + kk * 32 + lb);
                ldsm4(ah, base + off);
                ldsm4(al, base + 8192 + off);
#pragma unroll
                for (int nt = 0; nt < 8; ++nt) {
                    float* c = acc + (mt * 8 + nt) * 4;
                    mma16816(c, ah, bh + 2 * nt);
                    mma16816(c, ah, bl + 2 * nt);
                    mma16816(c, al, bh + 2 * nt);
                }
            }
        }
        if (s + 2 < 8)      CP_WAIT(1);
        else if (s + 1 < 8) CP_WAIT(0);
        cbuf = (cbuf == 2) ? 0 : cbuf + 1;
        lbuf = (lbuf == 2) ? 0 : lbuf + 1;
    }
    __syncthreads();

    float* sf = (float*)sb;
#pragma unroll
    for (int mt = 0; mt < 2; ++mt)
#pragma unroll
        for (int nt = 0; nt < 8; ++nt) {
            const float* c = acc + (mt * 8 + nt) * 4;
            int px0 = warpM * 32 + mt * 16 + (lane >> 2);
            int co0 = warpN * 64 + nt * 8 + (lane & 3) * 2;
            sf[co0 * 132 + px0]           = c[0];
            sf[(co0 + 1) * 132 + px0]     = c[1];
            sf[co0 * 132 + px0 + 8]       = c[2];
            sf[(co0 + 1) * 132 + px0 + 8] = c[3];
        }
    __syncthreads();

    const int b = nBase >> 10;
    const int p0 = nBase & 1023;
#pragma unroll 4
    for (int i = 0; i < 64; ++i) {
        int idx = t + i * 256;
        int co_l = idx >> 7;
        int px_l = idx & 127;
        int co = coBase + co_l;
        out[((size_t)b * 512 + 256 + co) * 1024 + p0 + px_l] =
            sf[co_l * 132 + px_l] + __ldg(&batt[co]);
    }
}

// ---------------------------------------------------------------------------
// prep_attn: split/scale/transpose q,k,v into MMA-friendly bf16 planes
// ---------------------------------------------------------------------------
__global__ __launch_bounds__(256) void prep_attn() {
    __shared__ float tq[32][33];
    __shared__ float tk[32][33];
    const int bh = blockIdx.y, b = bh >> 3, h = bh & 7;
    const int m0 = blockIdx.x * 32;
    const int t = threadIdx.x;
    const float QSC = 0.17677669529663687f * 1.4426950408889634f; // dkh^-.5 * log2e

#pragma unroll
    for (int i = 0; i < 4; ++i) {
        int idx = t + i * 256;
        int d = idx >> 5, mm = idx & 31;
        tq[d][mm] = g_qkv[((size_t)b * 768 + h * 32 + d) * 1024 + m0 + mm] * QSC;
        tk[d][mm] = g_qkv[((size_t)b * 768 + 256 + h * 32 + d) * 1024 + m0 + mm];
    }
    __syncthreads();
#pragma unroll
    for (int i = 0; i < 4; ++i) {
        int idx = t + i * 256;
        int mm = idx >> 5, d = idx & 31;
        float v = tq[d][mm];
        __nv_bfloat16 hi = __float2bfloat16(v);
        g_qh[((size_t)bh * 1024 + m0 + mm) * 32 + d] = hi;
        g_ql[((size_t)bh * 1024 + m0 + mm) * 32 + d] = __float2bfloat16(v - __bfloat162float(hi));
        v = tk[d][mm];
        hi = __float2bfloat16(v);
        g_kh[((size_t)bh * 1024 + m0 + mm) * 32 + d] = hi;
        g_kl[((size_t)bh * 1024 + m0 + mm) * 32 + d] = __float2bfloat16(v - __bfloat162float(hi));
    }
#pragma unroll
    for (int i = 0; i < 4; ++i) {
        int idx = t + i * 256;
        int d = idx >> 5, mm = idx & 31;
        float v = g_qkv[((size_t)b * 768 + 512 + h * 32 + d) * 1024 + m0 + mm];
        __nv_bfloat16 hi = __float2bfloat16(v);
        g_vh[((size_t)bh * 32 + d) * 1024 + m0 + mm] = hi;
        g_vl[((size_t)bh * 32 + d) * 1024 + m0 + mm] = __float2bfloat16(v - __bfloat162float(hi));
    }
}

// ---------------------------------------------------------------------------
// rel_k: rotated rel dots R_w'[m][ny] = q_s . krw[ny-qy+31], R_h' likewise
// ---------------------------------------------------------------------------
__global__ __launch_bounds__(256) void rel_k(
    const float* __restrict__ krw, const float* __restrict__ krh) {
    __shared__ float qs[128][32];
    __shared__ float kws[63][33];
    __shared__ float khs[63][33];
    const int bh = blockIdx.y;
    const int m0 = blockIdx.x * 128;
    const int t = threadIdx.x;

#pragma unroll
    for (int i = 0; i < 16; ++i) {
        int idx = t + i * 256;
        int mm = idx >> 5, d = idx & 31;
        size_t g = ((size_t)bh * 1024 + m0 + mm) * 32 + d;
        qs[mm][d] = __bfloat162float(g_qh[g]) + __bfloat162float(g_ql[g]);
    }
#pragma unroll
    for (int i = 0; i < 8; ++i) {
        int idx = t + i * 256;
        if (idx < 2016) {
            int r = idx >> 5, c = idx & 31;
            kws[r][c] = krw[idx];
            khs[r][c] = krh[idx];
        }
    }
    __syncthreads();

#pragma unroll 4
    for (int i = 0; i < 32; ++i) {
        int idx = t + i * 256;
        int mm = idx >> 6;
        int col = idx & 63;
        int half = col >> 5;
        int nyx = col & 31;
        int m = m0 + mm;
        int j = nyx - (half ? (m >> 5) : (m & 31)) + 31;
        const float* kr = half ? &khs[j][0] : &kws[j][0];
        float acc = 0.f;
#pragma unroll
        for (int d = 0; d < 32; ++d) acc += qs[mm][d] * kr[d];
        if (half)
            g_relh[((size_t)bh * 1024 + m) * 32 + nyx] = acc;
        else
            g_relw[((size_t)bh * 1024 + m) * 32 + nyx] = acc;
    }
}

// ---------------------------------------------------------------------------
// attn_mma: flash attention (R14 proven state)
// ---------------------------------------------------------------------------
__global__ __launch_bounds__(256, 2) void attn_mma() {
    extern __shared__ char dsm[];
    char* sb = (char*)(((uintptr_t)dsm + 1023) & ~(uintptr_t)1023);
    const uint32_t sbu = smem_u32(sb);
    const int t = threadIdx.x;
    const int lane = t & 31;
    const int w = t >> 5;
    const int bh = blockIdx.y, b = bh >> 3, h = bh & 7;
    const int m0 = blockIdx.x * 128;

    const uint32_t oQ = 32768, oRH = 49152;

#pragma unroll
    for (int i = 0; i < 2; ++i) {
        int idx = t + i * 256;
        int row = idx >> 2, j = idx & 3;
        uint32_t sw = SWZ64(row * 64 + j * 16);
        const char* sq = (const char*)g_qh + ((size_t)(bh * 1024 + m0 + row) * 32) * 2 + j * 16;
        const char* sl = (const char*)g_ql + ((size_t)(bh * 1024 + m0 + row) * 32) * 2 + j * 16;
        CP_ASYNC16(sbu + oQ + sw, sq);
        CP_ASYNC16(sbu + oQ + 8192 + sw, sl);
    }
#pragma unroll
    for (int i = 0; i < 4; ++i) {
        int idx = t + i * 256;
        int row = idx >> 3, j = idx & 7;
        const char* sr = (const char*)g_relh + ((size_t)(bh * 1024 + m0 + row) * 32) * 4 + j * 16;
        CP_ASYNC16(sbu + oRH + row * 144 + j * 16, sr);
    }
    CP_COMMIT();

#define LOAD_KV(buf, s_) do { \
        uint32_t b0 = sbu + (buf) * 16384; \
        int n0 = (s_) * 64; \
        { int row = t >> 2, j = t & 3; \
          uint32_t sw = SWZ64(row * 64 + j * 16); \
          CP_ASYNC16(b0 + sw, (const char*)g_kh + ((size_t)(bh * 1024 + n0 + row) * 32) * 2 + j * 16); \
          CP_ASYNC16(b0 + 4096 + sw, (const char*)g_kl + ((size_t)(bh * 1024 + n0 + row) * 32) * 2 + j * 16); } \
        { int row = t >> 3, j = t & 7; \
          uint32_t sw = SWZ128(row * 128 + j * 16); \
          CP_ASYNC16(b0 + 8192 + sw, (const char*)g_vh + ((size_t)(bh * 32 + row) * 1024 + n0) * 2 + j * 16); \
          CP_ASYNC16(b0 + 12288 + sw, (const char*)g_vl + ((size_t)(bh * 32 + row) * 1024 + n0) * 2 + j * 16); } \
    } while (0)

    LOAD_KV(0, 0);
    CP_COMMIT();
    CP_WAIT(0);
    __syncthreads();

    const int la = lane & 15;
    const int lb = (lane >> 4) << 4;
    const int bg = lane >> 3;
    const int brow = ((bg >> 1) << 3) + (lane & 7);
    const int bch = (bg & 1) << 4;
    const int rl = w * 16 + (lane >> 2);
    const int c0 = (lane & 3) * 2;

    uint32_t qh[2][4], ql[2][4];
    {
        int qrow = w * 16 + la;
#pragma unroll
        for (int ks = 0; ks < 2; ++ks) {
            uint32_t off = SWZ64(qrow * 64 + ks * 32 + lb);
            ldsm4(qh[ks], sbu + oQ + off);
            ldsm4(ql[ks], sbu + oQ + 8192 + off);
        }
    }
    float rwreg[2][8];
#pragma unroll
    for (int k2 = 0; k2 < 2; ++k2)
#pragma unroll
        for (int t2 = 0; t2 < 4; ++t2)
#pragma unroll
            for (int j = 0; j < 2; ++j)
                rwreg[k2][t2 * 2 + j] =
                    g_relw[((size_t)bh * 1024 + m0 + rl + k2 * 8) * 32 + t2 * 8 + c0 + j];

    const float* rhp = (const float*)(sb + oRH);

    float O[16];
#pragma unroll
    for (int i = 0; i < 16; ++i) O[i] = 0.f;
    float MA = -1e30f, MB = -1e30f, LA = 0.f, LB = 0.f;

#pragma unroll 1
    for (int s = 0; s < 16; ++s) {
        __syncthreads();
        if (s < 15) {
            LOAD_KV((s + 1) & 1, s + 1);
            CP_COMMIT();
        }

        const uint32_t kb = sbu + (s & 1) * 16384;

        float rhA0 = rhp[rl * 36 + s * 2];
        float rhA1 = rhp[rl * 36 + s * 2 + 1];
        float rhB0 = rhp[(rl + 8) * 36 + s * 2];
        float rhB1 = rhp[(rl + 8) * 36 + s * 2 + 1];
        float S[32];
#pragma unroll
        for (int t8 = 0; t8 < 8; ++t8) {
            int i2 = (t8 & 3) * 2;
            float ra = (t8 < 4) ? rhA0 : rhA1;
            float rb = (t8 < 4) ? rhB0 : rhB1;
            S[4 * t8 + 0] = rwreg[0][i2] + ra;
            S[4 * t8 + 1] = rwreg[0][i2 + 1] + ra;
            S[4 * t8 + 2] = rwreg[1][i2] + rb;
            S[4 * t8 + 3] = rwreg[1][i2 + 1] + rb;
        }

#pragma unroll
        for (int ks = 0; ks < 2; ++ks) {
#pragma unroll
            for (int gp = 0; gp < 2; ++gp) {
                uint32_t kfh[8], kfl[8];
#pragma unroll
                for (int g2 = 0; g2 < 2; ++g2) {
                    uint32_t off = SWZ64(((gp * 2 + g2) * 16 + brow) * 64 + ks * 32 + bch);
                    ldsm4(kfh + 4 * g2, kb + off);
                    ldsm4(kfl + 4 * g2, kb + 4096 + off);
                }
#pragma unroll
                for (int t4 = 0; t4 < 4; ++t4) {
                    float* c = S + 4 * (gp * 4 + t4);
                    mma16816(c, qh[ks], kfh + 2 * t4);
                    mma16816(c, qh[ks], kfl + 2 * t4);
                    mma16816(c, ql[ks], kfh + 2 * t4);
                }
            }
        }

        float mA = S[0], mB = S[2];
#pragma unroll
        for (int t8 = 0; t8 < 8; ++t8) {
            mA = fmaxf(mA, fmaxf(S[4 * t8], S[4 * t8 + 1]));
            mB = fmaxf(mB, fmaxf(S[4 * t8 + 2], S[4 * t8 + 3]));
        }
        mA = fmaxf(mA, __shfl_xor_sync(0xffffffffu, mA, 1));
        mA = fmaxf(mA, __shfl_xor_sync(0xffffffffu, mA, 2));
        mB = fmaxf(mB, __shfl_xor_sync(0xffffffffu, mB, 1));
        mB = fmaxf(mB, __shfl_xor_sync(0xffffffffu, mB, 2));
        float MA2 = fmaxf(MA, mA), MB2 = fmaxf(MB, mB);
        float aA = ex2(MA - MA2), aB = ex2(MB - MB2);
        MA = MA2; MB = MB2;

        float sA = 0.f, sB = 0.f;
#pragma unroll
        for (int t8 = 0; t8 < 8; ++t8) {
            S[4 * t8 + 0] = ex2(S[4 * t8 + 0] - MA);
            S[4 * t8 + 1] = ex2(S[4 * t8 + 1] - MA);
            S[4 * t8 + 2] = ex2(S[4 * t8 + 2] - MB);
            S[4 * t8 + 3] = ex2(S[4 * t8 + 3] - MB);
            sA += S[4 * t8] + S[4 * t8 + 1];
            sB += S[4 * t8 + 2] + S[4 * t8 + 3];
        }
        LA = LA * aA + sA;
        LB = LB * aB + sB;

#pragma unroll
        for (int dt = 0; dt < 4; ++dt) {
            O[4 * dt + 0] *= aA; O[4 * dt + 1] *= aA;
            O[4 * dt + 2] *= aB; O[4 * dt + 3] *= aB;
        }

        const uint32_t vb = kb + 8192;
#pragma unroll
        for (int k2 = 0; k2 < 4; ++k2) {
            uint32_t pah[4], pal[4];
#pragma unroll
            for (int q = 0; q < 4; ++q) {
                float p0 = S[8 * k2 + 2 * q];
                float p1 = S[8 * k2 + 2 * q + 1];
                uint32_t hp;
                asm("cvt.rn.bf16x2.f32 %0, %1, %2;" : "=r"(hp) : "f"(p1), "f"(p0));
                pah[q] = hp;
                float l0 = p0 - __uint_as_float(hp << 16);
                float l1 = p1 - __uint_as_float(hp & 0xffff0000u);
                uint32_t lp;
                asm("cvt.rn.bf16x2.f32 %0, %1, %2;" : "=r"(lp) : "f"(l1), "f"(l0));
                pal[q] = lp;
            }
            uint32_t vfh[8], vfl[8];
#pragma unroll
            for (int g = 0; g < 2; ++g) {
                uint32_t off = SWZ128((g * 16 + brow) * 128 + k2 * 32 + bch);
                ldsm4(vfh + 4 * g, vb + off);
                ldsm4(vfl + 4 * g, vb + 4096 + off);
            }
#pragma unroll
            for (int dt = 0; dt < 4; ++dt) {
                mma16816(O + 4 * dt, pah, vfh + 2 * dt);
                mma16816(O + 4 * dt, pah, vfl + 2 * dt);
                mma16816(O + 4 * dt, pal, vfh + 2 * dt);
            }
        }
        if (s < 15) CP_WAIT(0);
    }

    LA += __shfl_xor_sync(0xffffffffu, LA, 1);
    LA += __shfl_xor_sync(0xffffffffu, LA, 2);
    LB += __shfl_xor_sync(0xffffffffu, LB, 1);
    LB += __shfl_xor_sync(0xffffffffu, LB, 2);

    const float invA = 1.0f / LA;
    const float invB = 1.0f / LB;
    const int mA_g = m0 + rl;
    const int mB_g = mA_g + 8;
    const size_t offA = (size_t)b * 262144 + h * 32768 + (mA_g >> 5) * 1024 + (mA_g & 31) * 32 + c0;
    const size_t offB = (size_t)b * 262144 + h * 32768 + (mB_g >> 5) * 1024 + (mB_g & 31) * 32 + c0;
#pragma unroll
    for (int dt = 0; dt < 4; ++dt) {
        float2 va = make_float2(O[4 * dt] * invA, O[4 * dt + 1] * invA);
        float2 vbv = make_float2(O[4 * dt + 2] * invB, O[4 * dt + 3] * invB);
        *(float2*)&g_att[offA + dt * 8] = va;
        *(float2*)&g_att[offB + dt * 8] = vbv;
    }
}

// ---------------------------------------------------------------------------
// Launch (serial, R14 structure; conv_mma grid now 32x8)
// ---------------------------------------------------------------------------
extern "C" void kernel_launch(void* const* d_in, const int* in_sizes, int n_in,
                              void* d_out, int out_size) {
    const float* x      = (const float*)d_in[0];
    const float* w_conv = (const float*)d_in[1];
    const float* b_conv = (const float*)d_in[2];
    const float* w_qkv  = (const float*)d_in[3];
    const float* b_qkv  = (const float*)d_in[4];
    const float* w_att  = (const float*)d_in[5];
    const float* b_att  = (const float*)d_in[6];
    const float* krw    = (const float*)d_in[7];
    const float* krh    = (const float*)d_in[8];
    float* out = (float*)d_out;

    static int smem_set = 0;
    if (!smem_set) {
        cudaFuncSetAttribute(conv_mma, cudaFuncAttributeMaxDynamicSharedMemorySize, 99328);
        cudaFuncSetAttribute(conv1x1_mma, cudaFuncAttributeMaxDynamicSharedMemorySize, 99328);
        cudaFuncSetAttribute(attn_mma, cudaFuncAttributeMaxDynamicSharedMemorySize, 68608);
        smem_set = 1;
    }

    im2col_k<<<dim3(9, 8192), 256>>>(x);
    prep_w<<<dim3(9, 1024), 256>>>(w_conv, w_qkv);
    prep_watt<<<256, 256>>>(w_att);
    conv_mma<<<dim3(32, 8), 256, 99328>>>(b_conv, b_qkv, out);
    prep_attn<<<dim3(32, 64), 256>>>();
    rel_k<<<dim3(8, 64), 256>>>(krw, krh);
    attn_mma<<<dim3(8, 64), 256, 68608>>>();
    att_repack<<<dim3(32, 8, 8), 256>>>();
    conv1x1_mma<<<dim3(64, 2), 256, 99328>>>(b_att, out);
}

// round 17
// speedup vs baseline: 1.0388x; 1.0388x over previous
#include <cuda_runtime.h>
#include <cuda_bf16.h>
#include <cstdint>

// Problem: B=8, CIN=256, COUT=512, DK=DV=256, NH=8, H=W=32
// R17: exact R14 state (session-best 516.3us) + prep_watt folded into prep_w.

// Scratch (static device globals: allocation-free rule)
__device__ __nv_bfloat16 g_colh[8192 * 2304];  // im2col hi plane [n][k]
__device__ __nv_bfloat16 g_coll[8192 * 2304];  // im2col lo plane
__device__ __nv_bfloat16 g_wh[1024 * 2304];    // weights hi [co][k]
__device__ __nv_bfloat16 g_wl[1024 * 2304];    // weights lo
__device__ float g_qkv[8 * 768 * 1024];        // qkv conv output (b, 768, HW)
__device__ float g_att[8 * 256 * 1024];        // attention out, (b, C, H, W)

// attention operand planes
__device__ __nv_bfloat16 g_qh[64 * 1024 * 32]; // Q hi [bh][m][d] (scaled)
__device__ __nv_bfloat16 g_ql[64 * 1024 * 32];
__device__ __nv_bfloat16 g_kh[64 * 1024 * 32]; // K hi [bh][n][d]
__device__ __nv_bfloat16 g_kl[64 * 1024 * 32];
__device__ __nv_bfloat16 g_vh[64 * 32 * 1024]; // V hi [bh][d][n]
__device__ __nv_bfloat16 g_vl[64 * 32 * 1024];
__device__ float g_relw[64 * 1024 * 32];       // rotated rel-w [bh][m][ny]
__device__ float g_relh[64 * 1024 * 32];       // rotated rel-h [bh][m][nx]

// conv1x1 operand planes
__device__ __nv_bfloat16 g_atth[8192 * 256];   // att hi [b*1024+p][ci]
__device__ __nv_bfloat16 g_attl[8192 * 256];
__device__ __nv_bfloat16 g_wath[256 * 256];    // w_att hi [co][ci]
__device__ __nv_bfloat16 g_watl[256 * 256];

// ---------------------------------------------------------------------------
// Helpers (sm_80-era ISA only: cp.async, ldmatrix, mma.sync — safe on sm_103)
// ---------------------------------------------------------------------------
__device__ __forceinline__ uint32_t smem_u32(const void* p) {
    uint32_t a;
    asm("{ .reg .u64 t; cvta.to.shared.u64 t, %1; cvt.u32.u64 %0, t; }"
        : "=r"(a) : "l"(p));
    return a;
}
#define SWZ128(o) ((o) ^ (((o) >> 3) & 0x70))
#define SWZ64(o)  ((o) ^ (((o) >> 3) & 0x30))

#define CP_ASYNC16(dst, src) \
    asm volatile("cp.async.cg.shared.global [%0], [%1], 16;" :: "r"(dst), "l"(src))
#define CP_COMMIT() asm volatile("cp.async.commit_group;" ::: "memory")
#define CP_WAIT(n)  asm volatile("cp.async.wait_group %0;" :: "n"(n) : "memory")

__device__ __forceinline__ void ldsm4(uint32_t* r, uint32_t a) {
    asm volatile("ldmatrix.sync.aligned.m8n8.x4.shared.b16 {%0,%1,%2,%3}, [%4];"
                 : "=r"(r[0]), "=r"(r[1]), "=r"(r[2]), "=r"(r[3]) : "r"(a));
}
__device__ __forceinline__ void mma16816(float* c, const uint32_t* a, const uint32_t* b) {
    asm volatile(
        "mma.sync.aligned.m16n8k16.row.col.f32.bf16.bf16.f32 "
        "{%0,%1,%2,%3}, {%4,%5,%6,%7}, {%8,%9}, {%0,%1,%2,%3};"
        : "+f"(c[0]), "+f"(c[1]), "+f"(c[2]), "+f"(c[3])
        : "r"(a[0]), "r"(a[1]), "r"(a[2]), "r"(a[3]), "r"(b[0]), "r"(b[1]));
}
__device__ __forceinline__ float ex2(float x) {
    float y; asm("ex2.approx.f32 %0, %1;" : "=f"(y) : "f"(x)); return y;
}

// ---------------------------------------------------------------------------
// Prep kernels
// ---------------------------------------------------------------------------
__global__ void im2col_k(const float* __restrict__ x) {
    int k = blockIdx.x * 256 + threadIdx.x;   // 0..2303 (grid.x = 9)
    int n = blockIdx.y;                       // 0..8191
    int b = n >> 10, p = n & 1023, py = p >> 5, px = p & 31;
    int ci = k / 9, r = k - ci * 9;
    int ky = r / 3, kx = r - ky * 3;
    int gy = py + ky - 1, gx = px + kx - 1;
    float v = 0.f;
    if ((unsigned)gy < 32u && (unsigned)gx < 32u)
        v = x[((b * 256 + ci) * 32 + gy) * 32 + gx];
    __nv_bfloat16 hi = __float2bfloat16(v);
    float lo = v - __bfloat162float(hi);
    g_colh[(size_t)n * 2304 + k] = hi;
    g_coll[(size_t)n * 2304 + k] = __float2bfloat16(lo);
}

// prep_w also folds in the 1x1 weight split (blockIdx.x==0, blockIdx.y<256)
__global__ void prep_w(const float* __restrict__ wc, const float* __restrict__ wq,
                       const float* __restrict__ wa) {
    int k = blockIdx.x * 256 + threadIdx.x;   // grid.x = 9
    int co = blockIdx.y;                      // 0..1023
    float v = (co < 256) ? wc[co * 2304 + k] : wq[(co - 256) * 2304 + k];
    __nv_bfloat16 hi = __float2bfloat16(v);
    float lo = v - __bfloat162float(hi);
    g_wh[(size_t)co * 2304 + k] = hi;
    g_wl[(size_t)co * 2304 + k] = __float2bfloat16(lo);

    if (blockIdx.x == 0 && blockIdx.y < 256) {
        int idx = blockIdx.y * 256 + threadIdx.x;  // 0..65535, [co][ci]
        float va = wa[idx];
        __nv_bfloat16 hia = __float2bfloat16(va);
        g_wath[idx] = hia;
        g_watl[idx] = __float2bfloat16(va - __bfloat162float(hia));
    }
}

// att f32 [b][ci][p] -> bf16 hi/lo [b*1024+p][ci] (smem transpose)
__global__ __launch_bounds__(256) void att_repack() {
    __shared__ float ts[32][33];
    const int b = blockIdx.z;
    const int ci0 = blockIdx.y * 32;
    const int p0 = blockIdx.x * 32;
    const int t = threadIdx.x;
#pragma unroll
    for (int i = 0; i < 4; ++i) {
        int idx = t + i * 256;
        int ci_l = idx >> 5, p_l = idx & 31;
        ts[ci_l][p_l] = g_att[((size_t)b * 256 + ci0 + ci_l) * 1024 + p0 + p_l];
    }
    __syncthreads();
#pragma unroll
    for (int i = 0; i < 4; ++i) {
        int idx = t + i * 256;
        int p_l = idx >> 5, ci_l = idx & 31;
        float v = ts[ci_l][p_l];
        __nv_bfloat16 hi = __float2bfloat16(v);
        size_t o = ((size_t)b * 1024 + p0 + p_l) * 256 + ci0 + ci_l;
        g_atth[o] = hi;
        g_attl[o] = __float2bfloat16(v - __bfloat162float(hi));
    }
}

// ---------------------------------------------------------------------------
// conv3x3 split-bf16 GEMM. CTA tile 128px x 128co. K=2304 in 72 chunks of 32.
// 3-stage pipeline, one barrier per stage. (proven R14 local optimum)
// ---------------------------------------------------------------------------
__global__ __launch_bounds__(256, 2) void conv_mma(
    const float* __restrict__ bconv,
    const float* __restrict__ bqkv,
    float* __restrict__ out) {
    extern __shared__ char dsm[];
    char* sb = (char*)(((uintptr_t)dsm + 1023) & ~(uintptr_t)1023);
    const uint32_t sbu = smem_u32(sb);

    const int t = threadIdx.x;
    const int lane = t & 31;
    const int wid = t >> 5;
    const int warpM = wid >> 1;
    const int warpN = wid & 1;
    const int nBase = blockIdx.x * 128;
    const int coBase = blockIdx.y * 128;

    const int la = lane & 15;
    const int lb = (lane >> 4) << 4;
    const int bg = lane >> 3;
    const int brow = ((bg >> 1) << 3) + (lane & 7);
    const int bch = (bg & 1) << 4;

    float acc[64];
#pragma unroll
    for (int i = 0; i < 64; ++i) acc[i] = 0.f;

    const int lrow = t >> 2;
    const int lj = t & 3;

#define LOAD_STAGE32(buf, s_) do { \
        const size_t kb2 = (size_t)(s_) * 64; \
        uint32_t d0 = sbu + (buf) * 32768; \
        _Pragma("unroll") \
        for (int i = 0; i < 2; ++i) { \
            int row = lrow + i * 64; \
            uint32_t sw = SWZ64(row * 64 + lj * 16); \
            CP_ASYNC16(d0 + sw,         (const char*)g_colh + (size_t)(nBase + row) * 4608 + kb2 + lj * 16); \
            CP_ASYNC16(d0 + 8192 + sw,  (const char*)g_coll + (size_t)(nBase + row) * 4608 + kb2 + lj * 16); \
            CP_ASYNC16(d0 + 16384 + sw, (const char*)g_wh  + (size_t)(coBase + row) * 4608 + kb2 + lj * 16); \
            CP_ASYNC16(d0 + 24576 + sw, (const char*)g_wl  + (size_t)(coBase + row) * 4608 + kb2 + lj * 16); \
        } \
    } while (0)

    LOAD_STAGE32(0, 0);
    CP_COMMIT();
    LOAD_STAGE32(1, 1);
    CP_COMMIT();
    CP_WAIT(1);                    // stage 0 resident (own copies)

    int cbuf = 0;
    int lbuf = 2;
#pragma unroll 1
    for (int s = 0; s < 72; ++s) {
        __syncthreads();           // stage s visible to all; all warps done stage s-1
        if (s + 2 < 72) {
            LOAD_STAGE32(lbuf, s + 2);
            CP_COMMIT();
        }

        const uint32_t base = sbu + cbuf * 32768;
#pragma unroll
        for (int kk = 0; kk < 2; ++kk) {
            uint32_t bh[16], bl[16];
#pragma unroll
            for (int ntb = 0; ntb < 4; ++ntb) {
                uint32_t off = SWZ64((warpN * 64 + ntb * 16 + brow) * 64 + kk * 32 + bch);
                ldsm4(bh + 4 * ntb, base + 16384 + off);
                ldsm4(bl + 4 * ntb, base + 24576 + off);
            }
#pragma unroll
            for (int mt = 0; mt < 2; ++mt) {
                uint32_t ah[4], al[4];
                uint32_t off = SWZ64((warpM * 32 + mt * 16 + la) * 64 + kk * 32 + lb);
                ldsm4(ah, base + off);
                ldsm4(al, base + 8192 + off);
#pragma unroll
                for (int nt = 0; nt < 8; ++nt) {
                    float* c = acc + (mt * 8 + nt) * 4;
                    mma16816(c, ah, bh + 2 * nt);
                    mma16816(c, ah, bl + 2 * nt);
                    mma16816(c, al, bh + 2 * nt);
                }
            }
        }
        if (s + 2 < 72)      CP_WAIT(1);
        else if (s + 1 < 72) CP_WAIT(0);
        cbuf = (cbuf == 2) ? 0 : cbuf + 1;
        lbuf = (lbuf == 2) ? 0 : lbuf + 1;
    }
    __syncthreads();

    float* sf = (float*)sb;   // 128 co x 132 px (padded)
#pragma unroll
    for (int mt = 0; mt < 2; ++mt)
#pragma unroll
        for (int nt = 0; nt < 8; ++nt) {
            const float* c = acc + (mt * 8 + nt) * 4;
            int px0 = warpM * 32 + mt * 16 + (lane >> 2);
            int co0 = warpN * 64 + nt * 8 + (lane & 3) * 2;
            sf[co0 * 132 + px0]           = c[0];
            sf[(co0 + 1) * 132 + px0]     = c[1];
            sf[co0 * 132 + px0 + 8]       = c[2];
            sf[(co0 + 1) * 132 + px0 + 8] = c[3];
        }
    __syncthreads();

    const int b = nBase >> 10;
    const int p0 = nBase & 1023;
#pragma unroll 4
    for (int i = 0; i < 64; ++i) {
        int idx = t + i * 256;
        int co_l = idx >> 7;
        int px_l = idx & 127;
        float v = sf[co_l * 132 + px_l];
        int co = coBase + co_l;
        int p = p0 + px_l;
        if (coBase < 256) {
            out[((size_t)b * 512 + co) * 1024 + p] = v + __ldg(&bconv[co]);
        } else {
            g_qkv[((size_t)b * 768 + co - 256) * 1024 + p] = v + __ldg(&bqkv[co - 256]);
        }
    }
}

// ---------------------------------------------------------------------------
// conv1x1 split-bf16 GEMM. CTA tile 128px x 128co. K=256 in 8 chunks of 32.
// ---------------------------------------------------------------------------
__global__ __launch_bounds__(256, 2) void conv1x1_mma(
    const float* __restrict__ batt,
    float* __restrict__ out) {
    extern __shared__ char dsm[];
    char* sb = (char*)(((uintptr_t)dsm + 1023) & ~(uintptr_t)1023);
    const uint32_t sbu = smem_u32(sb);

    const int t = threadIdx.x;
    const int lane = t & 31;
    const int wid = t >> 5;
    const int warpM = wid >> 1;
    const int warpN = wid & 1;
    const int nBase = blockIdx.x * 128;
    const int coBase = blockIdx.y * 128;

    const int la = lane & 15;
    const int lb = (lane >> 4) << 4;
    const int bg = lane >> 3;
    const int brow = ((bg >> 1) << 3) + (lane & 7);
    const int bch = (bg & 1) << 4;

    float acc[64];
#pragma unroll
    for (int i = 0; i < 64; ++i) acc[i] = 0.f;

    const int lrow = t >> 2;
    const int lj = t & 3;

#define LOAD_STAGE1x1(buf, s_) do { \
        const size_t kb2 = (size_t)(s_) * 64; \
        uint32_t d0 = sbu + (buf) * 32768; \
        _Pragma("unroll") \
        for (int i = 0; i < 2; ++i) { \
            int row = lrow + i * 64; \
            uint32_t sw = SWZ64(row * 64 + lj * 16); \
            CP_ASYNC16(d0 + sw,         (const char*)g_atth + (size_t)(nBase + row) * 512 + kb2 + lj * 16); \
            CP_ASYNC16(d0 + 8192 + sw,  (const char*)g_attl + (size_t)(nBase + row) * 512 + kb2 + lj * 16); \
            CP_ASYNC16(d0 + 16384 + sw, (const char*)g_wath + (size_t)(coBase + row) * 512 + kb2 + lj * 16); \
            CP_ASYNC16(d0 + 24576 + sw, (const char*)g_watl + (size_t)(coBase + row) * 512 + kb2 + lj * 16); \
        } \
    } while (0)

    LOAD_STAGE1x1(0, 0);
    CP_COMMIT();
    LOAD_STAGE1x1(1, 1);
    CP_COMMIT();
    CP_WAIT(1);

    int cbuf = 0;
    int lbuf = 2;
#pragma unroll 1
    for (int s = 0; s < 8; ++s) {
        __syncthreads();
        if (s + 2 < 8) {
            LOAD_STAGE1x1(lbuf, s + 2);
            CP_COMMIT();
        }

        const uint32_t base = sbu + cbuf * 32768;
#pragma unroll
        for (int kk = 0; kk < 2; ++kk) {
            uint32_t bh[16], bl[16];
#pragma unroll
            for (int ntb = 0; ntb < 4; ++ntb) {
                uint32_t off = SWZ64((warpN * 64 + ntb * 16 + brow) * 64 + kk * 32 + bch);
                ldsm4(bh + 4 * ntb, base + 16384 + off);
                ldsm4(bl + 4 * ntb, base + 24576 + off);
            }
#pragma unroll
            for (int mt = 0; mt < 2; ++mt) {
                uint32_t ah[4], al[4];
                uint32_t off = SWZ64((warpM * 32 + mt * 16 + la) * 64 + kk * 32 + lb);
                ldsm4(ah, base + off);
                ldsm4(al, base + 8192 + off);
#pragma unroll
                for (int nt = 0; nt < 8; ++nt) {
                    float* c = acc + (mt * 8 + nt) * 4;
                    mma16816(c, ah, bh + 2 * nt);
                    mma16816(c, ah, bl + 2 * nt);
                    mma16816(c, al, bh + 2 * nt);
                }
            }
        }
        if (s + 2 < 8)      CP_WAIT(1);
        else if (s + 1 < 8) CP_WAIT(0);
        cbuf = (cbuf == 2) ? 0 : cbuf + 1;
        lbuf = (lbuf == 2) ? 0 : lbuf + 1;
    }
    __syncthreads();

    float* sf = (float*)sb;
#pragma unroll
    for (int mt = 0; mt < 2; ++mt)
#pragma unroll
        for (int nt = 0; nt < 8; ++nt) {
            const float* c = acc + (mt * 8 + nt) * 4;
            int px0 = warpM * 32 + mt * 16 + (lane >> 2);
            int co0 = warpN * 64 + nt * 8 + (lane & 3) * 2;
            sf[co0 * 132 + px0]           = c[0];
            sf[(co0 + 1) * 132 + px0]     = c[1];
            sf[co0 * 132 + px0 + 8]       = c[2];
            sf[(co0 + 1) * 132 + px0 + 8] = c[3];
        }
    __syncthreads();

    const int b = nBase >> 10;
    const int p0 = nBase & 1023;
#pragma unroll 4
    for (int i = 0; i < 64; ++i) {
        int idx = t + i * 256;
        int co_l = idx >> 7;
        int px_l = idx & 127;
        int co = coBase + co_l;
        out[((size_t)b * 512 + 256 + co) * 1024 + p0 + px_l] =
            sf[co_l * 132 + px_l] + __ldg(&batt[co]);
    }
}

// ---------------------------------------------------------------------------
// prep_attn: split/scale/transpose q,k,v into MMA-friendly bf16 planes
// ---------------------------------------------------------------------------
__global__ __launch_bounds__(256) void prep_attn() {
    __shared__ float tq[32][33];
    __shared__ float tk[32][33];
    const int bh = blockIdx.y, b = bh >> 3, h = bh & 7;
    const int m0 = blockIdx.x * 32;
    const int t = threadIdx.x;
    const float QSC = 0.17677669529663687f * 1.4426950408889634f; // dkh^-.5 * log2e

#pragma unroll
    for (int i = 0; i < 4; ++i) {
        int idx = t + i * 256;
        int d = idx >> 5, mm = idx & 31;
        tq[d][mm] = g_qkv[((size_t)b * 768 + h * 32 + d) * 1024 + m0 + mm] * QSC;
        tk[d][mm] = g_qkv[((size_t)b * 768 + 256 + h * 32 + d) * 1024 + m0 + mm];
    }
    __syncthreads();
#pragma unroll
    for (int i = 0; i < 4; ++i) {
        int idx = t + i * 256;
        int mm = idx >> 5, d = idx & 31;
        float v = tq[d][mm];
        __nv_bfloat16 hi = __float2bfloat16(v);
        g_qh[((size_t)bh * 1024 + m0 + mm) * 32 + d] = hi;
        g_ql[((size_t)bh * 1024 + m0 + mm) * 32 + d] = __float2bfloat16(v - __bfloat162float(hi));
        v = tk[d][mm];
        hi = __float2bfloat16(v);
        g_kh[((size_t)bh * 1024 + m0 + mm) * 32 + d] = hi;
        g_kl[((size_t)bh * 1024 + m0 + mm) * 32 + d] = __float2bfloat16(v - __bfloat162float(hi));
    }
#pragma unroll
    for (int i = 0; i < 4; ++i) {
        int idx = t + i * 256;
        int d = idx >> 5, mm = idx & 31;
        float v = g_qkv[((size_t)b * 768 + 512 + h * 32 + d) * 1024 + m0 + mm];
        __nv_bfloat16 hi = __float2bfloat16(v);
        g_vh[((size_t)bh * 32 + d) * 1024 + m0 + mm] = hi;
        g_vl[((size_t)bh * 32 + d) * 1024 + m0 + mm] = __float2bfloat16(v - __bfloat162float(hi));
    }
}

// ---------------------------------------------------------------------------
// rel_k: rotated rel dots R_w'[m][ny] = q_s . krw[ny-qy+31], R_h' likewise
// ---------------------------------------------------------------------------
__global__ __launch_bounds__(256) void rel_k(
    const float* __restrict__ krw, const float* __restrict__ krh) {
    __shared__ float qs[128][32];
    __shared__ float kws[63][33];
    __shared__ float khs[63][33];
    const int bh = blockIdx.y;
    const int m0 = blockIdx.x * 128;
    const int t = threadIdx.x;

#pragma unroll
    for (int i = 0; i < 16; ++i) {
        int idx = t + i * 256;
        int mm = idx >> 5, d = idx & 31;
        size_t g = ((size_t)bh * 1024 + m0 + mm) * 32 + d;
        qs[mm][d] = __bfloat162float(g_qh[g]) + __bfloat162float(g_ql[g]);
    }
#pragma unroll
    for (int i = 0; i < 8; ++i) {
        int idx = t + i * 256;
        if (idx < 2016) {
            int r = idx >> 5, c = idx & 31;
            kws[r][c] = krw[idx];
            khs[r][c] = krh[idx];
        }
    }
    __syncthreads();

#pragma unroll 4
    for (int i = 0; i < 32; ++i) {
        int idx = t + i * 256;
        int mm = idx >> 6;
        int col = idx & 63;
        int half = col >> 5;
        int nyx = col & 31;
        int m = m0 + mm;
        int j = nyx - (half ? (m >> 5) : (m & 31)) + 31;
        const float* kr = half ? &khs[j][0] : &kws[j][0];
        float acc = 0.f;
#pragma unroll
        for (int d = 0; d < 32; ++d) acc += qs[mm][d] * kr[d];
        if (half)
            g_relh[((size_t)bh * 1024 + m) * 32 + nyx] = acc;
        else
            g_relw[((size_t)bh * 1024 + m) * 32 + nyx] = acc;
    }
}

// ---------------------------------------------------------------------------
// attn_mma: flash attention (R14 proven state)
// ---------------------------------------------------------------------------
__global__ __launch_bounds__(256, 2) void attn_mma() {
    extern __shared__ char dsm[];
    char* sb = (char*)(((uintptr_t)dsm + 1023) & ~(uintptr_t)1023);
    const uint32_t sbu = smem_u32(sb);
    const int t = threadIdx.x;
    const int lane = t & 31;
    const int w = t >> 5;
    const int bh = blockIdx.y, b = bh >> 3, h = bh & 7;
    const int m0 = blockIdx.x * 128;

    const uint32_t oQ = 32768, oRH = 49152;

#pragma unroll
    for (int i = 0; i < 2; ++i) {
        int idx = t + i * 256;
        int row = idx >> 2, j = idx & 3;
        uint32_t sw = SWZ64(row * 64 + j * 16);
        const char* sq = (const char*)g_qh + ((size_t)(bh * 1024 + m0 + row) * 32) * 2 + j * 16;
        const char* sl = (const char*)g_ql + ((size_t)(bh * 1024 + m0 + row) * 32) * 2 + j * 16;
        CP_ASYNC16(sbu + oQ + sw, sq);
        CP_ASYNC16(sbu + oQ + 8192 + sw, sl);
    }
#pragma unroll
    for (int i = 0; i < 4; ++i) {
        int idx = t + i * 256;
        int row = idx >> 3, j = idx & 7;
        const char* sr = (const char*)g_relh + ((size_t)(bh * 1024 + m0 + row) * 32) * 4 + j * 16;
        CP_ASYNC16(sbu + oRH + row * 144 + j * 16, sr);
    }
    CP_COMMIT();

#define LOAD_KV(buf, s_) do { \
        uint32_t b0 = sbu + (buf) * 16384; \
        int n0 = (s_) * 64; \
        { int row = t >> 2, j = t & 3; \
          uint32_t sw = SWZ64(row * 64 + j * 16); \
          CP_ASYNC16(b0 + sw, (const char*)g_kh + ((size_t)(bh * 1024 + n0 + row) * 32) * 2 + j * 16); \
          CP_ASYNC16(b0 + 4096 + sw, (const char*)g_kl + ((size_t)(bh * 1024 + n0 + row) * 32) * 2 + j * 16); } \
        { int row = t >> 3, j = t & 7; \
          uint32_t sw = SWZ128(row * 128 + j * 16); \
          CP_ASYNC16(b0 + 8192 + sw, (const char*)g_vh + ((size_t)(bh * 32 + row) * 1024 + n0) * 2 + j * 16); \
          CP_ASYNC16(b0 + 12288 + sw, (const char*)g_vl + ((size_t)(bh * 32 + row) * 1024 + n0) * 2 + j * 16); } \
    } while (0)

    LOAD_KV(0, 0);
    CP_COMMIT();
    CP_WAIT(0);
    __syncthreads();

    const int la = lane & 15;
    const int lb = (lane >> 4) << 4;
    const int bg = lane >> 3;
    const int brow = ((bg >> 1) << 3) + (lane & 7);
    const int bch = (bg & 1) << 4;
    const int rl = w * 16 + (lane >> 2);
    const int c0 = (lane & 3) * 2;

    uint32_t qh[2][4], ql[2][4];
    {
        int qrow = w * 16 + la;
#pragma unroll
        for (int ks = 0; ks < 2; ++ks) {
            uint32_t off = SWZ64(qrow * 64 + ks * 32 + lb);
            ldsm4(qh[ks], sbu + oQ + off);
            ldsm4(ql[ks], sbu + oQ + 8192 + off);
        }
    }
    float rwreg[2][8];
#pragma unroll
    for (int k2 = 0; k2 < 2; ++k2)
#pragma unroll
        for (int t2 = 0; t2 < 4; ++t2)
#pragma unroll
            for (int j = 0; j < 2; ++j)
                rwreg[k2][t2 * 2 + j] =
                    g_relw[((size_t)bh * 1024 + m0 + rl + k2 * 8) * 32 + t2 * 8 + c0 + j];

    const float* rhp = (const float*)(sb + oRH);

    float O[16];
#pragma unroll
    for (int i = 0; i < 16; ++i) O[i] = 0.f;
    float MA = -1e30f, MB = -1e30f, LA = 0.f, LB = 0.f;

#pragma unroll 1
    for (int s = 0; s < 16; ++s) {
        __syncthreads();
        if (s < 15) {
            LOAD_KV((s + 1) & 1, s + 1);
            CP_COMMIT();
        }

        const uint32_t kb = sbu + (s & 1) * 16384;

        float rhA0 = rhp[rl * 36 + s * 2];
        float rhA1 = rhp[rl * 36 + s * 2 + 1];
        float rhB0 = rhp[(rl + 8) * 36 + s * 2];
        float rhB1 = rhp[(rl + 8) * 36 + s * 2 + 1];
        float S[32];
#pragma unroll
        for (int t8 = 0; t8 < 8; ++t8) {
            int i2 = (t8 & 3) * 2;
            float ra = (t8 < 4) ? rhA0 : rhA1;
            float rb = (t8 < 4) ? rhB0 : rhB1;
            S[4 * t8 + 0] = rwreg[0][i2] + ra;
            S[4 * t8 + 1] = rwreg[0][i2 + 1] + ra;
            S[4 * t8 + 2] = rwreg[1][i2] + rb;
            S[4 * t8 + 3] = rwreg[1][i2 + 1] + rb;
        }

#pragma unroll
        for (int ks = 0; ks < 2; ++ks) {
#pragma unroll
            for (int gp = 0; gp < 2; ++gp) {
                uint32_t kfh[8], kfl[8];
#pragma unroll
                for (int g2 = 0; g2 < 2; ++g2) {
                    uint32_t off = SWZ64(((gp * 2 + g2) * 16 + brow) * 64 + ks * 32 + bch);
                    ldsm4(kfh + 4 * g2, kb + off);
                    ldsm4(kfl + 4 * g2, kb + 4096 + off);
                }
#pragma unroll
                for (int t4 = 0; t4 < 4; ++t4) {
                    float* c = S + 4 * (gp * 4 + t4);
                    mma16816(c, qh[ks], kfh + 2 * t4);
                    mma16816(c, qh[ks], kfl + 2 * t4);
                    mma16816(c, ql[ks], kfh + 2 * t4);
                }
            }
        }

        float mA = S[0], mB = S[2];
#pragma unroll
        for (int t8 = 0; t8 < 8; ++t8) {
            mA = fmaxf(mA, fmaxf(S[4 * t8], S[4 * t8 + 1]));
            mB = fmaxf(mB, fmaxf(S[4 * t8 + 2], S[4 * t8 + 3]));
        }
        mA = fmaxf(mA, __shfl_xor_sync(0xffffffffu, mA, 1));
        mA = fmaxf(mA, __shfl_xor_sync(0xffffffffu, mA, 2));
        mB = fmaxf(mB, __shfl_xor_sync(0xffffffffu, mB, 1));
        mB = fmaxf(mB, __shfl_xor_sync(0xffffffffu, mB, 2));
        float MA2 = fmaxf(MA, mA), MB2 = fmaxf(MB, mB);
        float aA = ex2(MA - MA2), aB = ex2(MB - MB2);
        MA = MA2; MB = MB2;

        float sA = 0.f, sB = 0.f;
#pragma unroll
        for (int t8 = 0; t8 < 8; ++t8) {
            S[4 * t8 + 0] = ex2(S[4 * t8 + 0] - MA);
            S[4 * t8 + 1] = ex2(S[4 * t8 + 1] - MA);
            S[4 * t8 + 2] = ex2(S[4 * t8 + 2] - MB);
            S[4 * t8 + 3] = ex2(S[4 * t8 + 3] - MB);
            sA += S[4 * t8] + S[4 * t8 + 1];
            sB += S[4 * t8 + 2] + S[4 * t8 + 3];
        }
        LA = LA * aA + sA;
        LB = LB * aB + sB;

#pragma unroll
        for (int dt = 0; dt < 4; ++dt) {
            O[4 * dt + 0] *= aA; O[4 * dt + 1] *= aA;
            O[4 * dt + 2] *= aB; O[4 * dt + 3] *= aB;
        }

        const uint32_t vb = kb + 8192;
#pragma unroll
        for (int k2 = 0; k2 < 4; ++k2) {
            uint32_t pah[4], pal[4];
#pragma unroll
            for (int q = 0; q < 4; ++q) {
                float p0 = S[8 * k2 + 2 * q];
                float p1 = S[8 * k2 + 2 * q + 1];
                uint32_t hp;
                asm("cvt.rn.bf16x2.f32 %0, %1, %2;" : "=r"(hp) : "f"(p1), "f"(p0));
                pah[q] = hp;
                float l0 = p0 - __uint_as_float(hp << 16);
                float l1 = p1 - __uint_as_float(hp & 0xffff0000u);
                uint32_t lp;
                asm("cvt.rn.bf16x2.f32 %0, %1, %2;" : "=r"(lp) : "f"(l1), "f"(l0));
                pal[q] = lp;
            }
            uint32_t vfh[8], vfl[8];
#pragma unroll
            for (int g = 0; g < 2; ++g) {
                uint32_t off = SWZ128((g * 16 + brow) * 128 + k2 * 32 + bch);
                ldsm4(vfh + 4 * g, vb + off);
                ldsm4(vfl + 4 * g, vb + 4096 + off);
            }
#pragma unroll
            for (int dt = 0; dt < 4; ++dt) {
                mma16816(O + 4 * dt, pah, vfh + 2 * dt);
                mma16816(O + 4 * dt, pah, vfl + 2 * dt);
                mma16816(O + 4 * dt, pal, vfh + 2 * dt);
            }
        }
        if (s < 15) CP_WAIT(0);
    }

    LA += __shfl_xor_sync(0xffffffffu, LA, 1);
    LA += __shfl_xor_sync(0xffffffffu, LA, 2);
    LB += __shfl_xor_sync(0xffffffffu, LB, 1);
    LB += __shfl_xor_sync(0xffffffffu, LB, 2);

    const float invA = 1.0f / LA;
    const float invB = 1.0f / LB;
    const int mA_g = m0 + rl;
    const int mB_g = mA_g + 8;
    const size_t offA = (size_t)b * 262144 + h * 32768 + (mA_g >> 5) * 1024 + (mA_g & 31) * 32 + c0;
    const size_t offB = (size_t)b * 262144 + h * 32768 + (mB_g >> 5) * 1024 + (mB_g & 31) * 32 + c0;
#pragma unroll
    for (int dt = 0; dt < 4; ++dt) {
        float2 va = make_float2(O[4 * dt] * invA, O[4 * dt + 1] * invA);
        float2 vbv = make_float2(O[4 * dt + 2] * invB, O[4 * dt + 3] * invB);
        *(float2*)&g_att[offA + dt * 8] = va;
        *(float2*)&g_att[offB + dt * 8] = vbv;
    }
}

// ---------------------------------------------------------------------------
// Launch (serial, R14 structure; prep_watt folded into prep_w)
// ---------------------------------------------------------------------------
extern "C" void kernel_launch(void* const* d_in, const int* in_sizes, int n_in,
                              void* d_out, int out_size) {
    const float* x      = (const float*)d_in[0];
    const float* w_conv = (const float*)d_in[1];
    const float* b_conv = (const float*)d_in[2];
    const float* w_qkv  = (const float*)d_in[3];
    const float* b_qkv  = (const float*)d_in[4];
    const float* w_att  = (const float*)d_in[5];
    const float* b_att  = (const float*)d_in[6];
    const float* krw    = (const float*)d_in[7];
    const float* krh    = (const float*)d_in[8];
    float* out = (float*)d_out;

    static int smem_set = 0;
    if (!smem_set) {
        cudaFuncSetAttribute(conv_mma, cudaFuncAttributeMaxDynamicSharedMemorySize, 99328);
        cudaFuncSetAttribute(conv1x1_mma, cudaFuncAttributeMaxDynamicSharedMemorySize, 99328);
        cudaFuncSetAttribute(attn_mma, cudaFuncAttributeMaxDynamicSharedMemorySize, 68608);
        smem_set = 1;
    }

    im2col_k<<<dim3(9, 8192), 256>>>(x);
    prep_w<<<dim3(9, 1024), 256>>>(w_conv, w_qkv, w_att);
    conv_mma<<<dim3(64, 8), 256, 99328>>>(b_conv, b_qkv, out);
    prep_attn<<<dim3(32, 64), 256>>>();
    rel_k<<<dim3(8, 64), 256>>>(krw, krh);
    attn_mma<<<dim3(8, 64), 256, 68608>>>();
    att_repack<<<dim3(32, 8, 8), 256>>>();
    conv1x1_mma<<<dim3(64, 2), 256, 99328>>>(b_att, out);
}